// round 11
// baseline (speedup 1.0000x reference)
#include <cuda_runtime.h>
#include <cmath>
#include <complex>

// ============================================================================
// Selfmix: SO(3) self tensor product, LMAX=2, B x 1152 -> B x 3200 (fp32).
// R10 (final): R9 config — packed f32x2 body, per-section scale loads,
// write-through stores — with block=256. Kernel family is at the measured
// DRAM-write floor (~5.3 TB/s for the 93%-write stream, 226 MB minimal
// traffic); all SM-side knobs verified neutral across R2-R9.
// ============================================================================

using u64 = unsigned long long;

// ---------------- packed f32x2 primitives (PTX-only on sm_103a) -------------
__device__ __forceinline__ u64 fma2(u64 a, u64 b, u64 c) {
  u64 d;
  asm("fma.rn.f32x2 %0, %1, %2, %3;" : "=l"(d) : "l"(a), "l"(b), "l"(c));
  return d;
}
__device__ __forceinline__ u64 mul2(u64 a, u64 b) {
  u64 d;
  asm("mul.rn.f32x2 %0, %1, %2;" : "=l"(d) : "l"(a), "l"(b));
  return d;
}
__device__ __forceinline__ u64 add2(u64 a, u64 b) {
  u64 d;
  asm("add.rn.f32x2 %0, %1, %2;" : "=l"(d) : "l"(a), "l"(b));
  return d;
}
__device__ __forceinline__ u64 pack2(float lo, float hi) {
  u64 d;
  asm("mov.b64 %0, {%1, %2};" : "=l"(d) : "f"(lo), "f"(hi));
  return d;
}
// write-through 64-bit store
__device__ __forceinline__ void stwt64(u64* ptr, u64 v) {
  asm volatile("st.global.wt.b64 [%0], %1;" :: "l"(ptr), "l"(v) : "memory");
}

// ---------------- compile-time structural nonzero mask ----------------------
__host__ __device__ constexpr bool structural(int l1, int l2, int lo,
                                              int a, int b, int c) {
  const int ma = a - l1, mb = b - l2, mc = c - lo;
  const int x = ma < 0 ? -ma : ma;
  const int y = mb < 0 ? -mb : mb;
  const int z = mc < 0 ? -mc : mc;
  const bool abs_ok = (z == x + y) || (z == (x > y ? x - y : y - x));
  const int nsin = (ma < 0 ? 1 : 0) + (mb < 0 ? 1 : 0) + (mc < 0 ? 1 : 0);
  const bool par_ok = ((nsin & 1) == ((l1 + l2 + lo) & 1));
  return abs_ok && par_ok;
}

// ---------------- by-value parameter block (constant bank) ------------------
// Each CG coefficient duplicated: float2{w, w} -> one 64-bit packed operand.
struct Params {
  float2 c000[1][1][1];
  float2 c110[3][3][1];
  float2 c220[5][5][1];
  float2 c011[1][3][3];
  float2 c121[3][5][3];
  float2 c022[1][5][5];
  float2 c112[3][3][5];
  float2 c122[3][5][5];
  float2 c222[5][5][5];
  float2 c123[3][5][7];
  float2 c224[5][5][9];
};  // 689 float2 = 5512 bytes

// ---------------- per-combo contraction, fully unrolled, packed -------------
template <int L1, int L2, int LO>
__device__ __forceinline__ void combo(
    const float2 (&cg)[2 * L1 + 1][2 * L2 + 1][2 * LO + 1],
    const u64 (&xa)[2 * L1 + 1],
    const u64 (&xb)[2 * L2 + 1],
    u64 (&out)[2 * LO + 1],
    u64 s) {
  u64 ya[2 * L1 + 1];
#pragma unroll
  for (int a = 0; a < 2 * L1 + 1; a++) ya[a] = mul2(xa[a], s);
#pragma unroll
  for (int a = 0; a < 2 * L1 + 1; a++) {
#pragma unroll
    for (int b = 0; b < 2 * L2 + 1; b++) {
      bool any = false;
#pragma unroll
      for (int c = 0; c < 2 * LO + 1; c++) any = any || structural(L1, L2, LO, a, b, c);
      if (any) {  // compile-time constant after unroll
        const u64 p = mul2(ya[a], xb[b]);
#pragma unroll
        for (int c = 0; c < 2 * LO + 1; c++) {
          if (structural(L1, L2, LO, a, b, c)) {
            const u64 w = *reinterpret_cast<const u64*>(&cg[a][b][c]);
            out[c] = fma2(w, p, out[c]);
          }
        }
      }
    }
  }
}

// ---------------- kernel: one thread = one (b, channel-pair) ----------------
__global__ __launch_bounds__(256) void selfmix_kernel(
    const u64* __restrict__ x, const u64* __restrict__ keep,
    const u64* __restrict__ mix, u64* __restrict__ out,
    int nthreads, const __grid_constant__ Params p) {
  const int t = blockIdx.x * 256 + threadIdx.x;
  if (t >= nthreads) return;
  const int b = t >> 6;       // batch row
  const int cp = t & 63;      // channel pair (channels 2cp, 2cp+1)

  // ---- load inputs (64-bit packed, fully coalesced) ----
  const u64* xr = x + (size_t)b * 576;
  u64 X0[1], X1[3], X2[5];
  X0[0] = xr[cp];
#pragma unroll
  for (int m = 0; m < 3; m++) X1[m] = xr[64 + m * 64 + cp];
#pragma unroll
  for (int m = 0; m < 5; m++) X2[m] = xr[256 + m * 64 + cp];

  const u64 HALF = pack2(0.5f, 0.5f);
  const u64 NHALF = pack2(-0.5f, -0.5f);
  u64* orow = out + (size_t)b * 1600;

  // ---- lo = 4 : (2,2->4) ----
  {
    const u64 s224 = mul2(mix[18 * 64 + cp], HALF);
    u64 O[9] = {};
    combo<2, 2, 4>(p.c224, X2, X2, O, s224);
#pragma unroll
    for (int k = 0; k < 9; k++) stwt64(orow + 1024 + k * 64 + cp, O[k]);
  }
  // ---- lo = 3 : (1,2->3)+(2,1->3) merged (sigma=+1) ----
  {
    const u64 s123 = mul2(add2(mix[15 * 64 + cp], mix[16 * 64 + cp]), HALF);
    u64 O[7] = {};
    combo<1, 2, 3>(p.c123, X1, X2, O, s123);
#pragma unroll
    for (int k = 0; k < 7; k++) stwt64(orow + 576 + k * 64 + cp, O[k]);
  }
  // ---- lo = 2 : (0,2)+(2,0), (1,1), (1,2)-(2,1), (2,2) + keep ----
  {
    const u64 s022 = mul2(add2(mix[9 * 64 + cp], mix[12 * 64 + cp]), HALF);
    const u64 s112 = mul2(mix[10 * 64 + cp], HALF);
    const u64 s122 = fma2(mix[13 * 64 + cp], NHALF,
                          mul2(mix[11 * 64 + cp], HALF));
    const u64 s222 = mul2(mix[14 * 64 + cp], HALF);
    const u64 k2 = keep[128 + cp];
    u64 O[5] = {};
    combo<0, 2, 2>(p.c022, X0, X2, O, s022);
    combo<1, 1, 2>(p.c112, X1, X1, O, s112);
    combo<1, 2, 2>(p.c122, X1, X2, O, s122);
    combo<2, 2, 2>(p.c222, X2, X2, O, s222);
#pragma unroll
    for (int k = 0; k < 5; k++) {
      O[k] = fma2(X2[k], k2, O[k]);
      stwt64(orow + 256 + k * 64 + cp, O[k]);
    }
  }
  // ---- lo = 1 : (0,1)+(1,0), (1,2)+(2,1) + keep ----
  {
    const u64 s011 = mul2(add2(mix[3 * 64 + cp], mix[4 * 64 + cp]), HALF);
    const u64 s121 = mul2(add2(mix[6 * 64 + cp], mix[7 * 64 + cp]), HALF);
    const u64 k1 = keep[64 + cp];
    u64 O[3] = {};
    combo<0, 1, 1>(p.c011, X0, X1, O, s011);
    combo<1, 2, 1>(p.c121, X1, X2, O, s121);
#pragma unroll
    for (int k = 0; k < 3; k++) {
      O[k] = fma2(X1[k], k1, O[k]);
      stwt64(orow + 64 + k * 64 + cp, O[k]);
    }
  }
  // ---- lo = 0 : (0,0), (1,1), (2,2) + keep ----
  {
    const u64 s000 = mul2(mix[0 * 64 + cp], HALF);
    const u64 s110 = mul2(mix[1 * 64 + cp], HALF);
    const u64 s220 = mul2(mix[2 * 64 + cp], HALF);
    const u64 k0 = keep[cp];
    u64 O[1] = {};
    combo<0, 0, 0>(p.c000, X0, X0, O, s000);
    combo<1, 1, 0>(p.c110, X1, X1, O, s110);
    combo<2, 2, 0>(p.c220, X2, X2, O, s220);
    O[0] = fma2(X0[0], k0, O[0]);
    stwt64(orow + cp, O[0]);
  }
}

// ============================================================================
// Host: exact port of the reference CG construction (Racah + real basis).
// ============================================================================
static double factd(int n) {
  double r = 1.0;
  for (int i = 2; i <= n; i++) r *= (double)i;
  return r;
}

static void cg_complex_h(int l1, int l2, int l3, double C[5][5][9]) {
  for (int i = 0; i < 5; i++)
    for (int j = 0; j < 5; j++)
      for (int k = 0; k < 9; k++) C[i][j][k] = 0.0;
  for (int m1 = -l1; m1 <= l1; m1++) {
    for (int m2 = -l2; m2 <= l2; m2++) {
      const int m3 = m1 + m2;
      if (m3 < -l3 || m3 > l3) continue;
      double pre = std::sqrt((2 * l3 + 1) * factd(l1 + l2 - l3) * factd(l1 - l2 + l3) *
                             factd(-l1 + l2 + l3) / factd(l1 + l2 + l3 + 1));
      pre *= std::sqrt(factd(l3 + m3) * factd(l3 - m3) * factd(l1 - m1) *
                       factd(l1 + m1) * factd(l2 - m2) * factd(l2 + m2));
      double s = 0.0;
      for (int k = 0; k <= l1 + l2 - l3; k++) {
        const int den[6] = {k, l1 + l2 - l3 - k, l1 - m1 - k, l2 + m2 - k,
                            l3 - l2 + m1 + k, l3 - l1 - m2 + k};
        int mn = den[0];
        for (int t = 1; t < 6; t++) mn = den[t] < mn ? den[t] : mn;
        if (mn < 0) continue;
        double d = 1.0;
        for (int t = 0; t < 6; t++) d *= factd(den[t]);
        s += ((k & 1) ? -1.0 : 1.0) / d;
      }
      C[m1 + l1][m2 + l2][m3 + l3] = pre * s;
    }
  }
}

static void build_u(int l, std::complex<double> U[9][9]) {
  for (int i = 0; i < 9; i++)
    for (int j = 0; j < 9; j++) U[i][j] = 0.0;
  U[l][l] = 1.0;
  const double is2 = 1.0 / std::sqrt(2.0);
  for (int m = 1; m <= l; m++) {
    const double sgn = (m & 1) ? -1.0 : 1.0;
    U[l + m][l + m] = sgn * is2;
    U[l + m][l - m] = is2;
    U[l - m][l - m] = std::complex<double>(0.0, is2);
    U[l - m][l + m] = std::complex<double>(0.0, -sgn * is2);
  }
}

static void cg_real_h(int l1, int l2, int l3, float2* R) {
  const int d1 = 2 * l1 + 1, d2 = 2 * l2 + 1, d3 = 2 * l3 + 1;
  double C[5][5][9];
  cg_complex_h(l1, l2, l3, C);
  std::complex<double> U1[9][9], U2[9][9], U3[9][9];
  build_u(l1, U1);
  build_u(l2, U2);
  build_u(l3, U3);
  double Rre[5][5][9], Rim[5][5][9];
  double mxre = 0.0, mxim = 0.0;
  for (int a = 0; a < d1; a++) {
    for (int b = 0; b < d2; b++) {
      for (int c = 0; c < d3; c++) {
        std::complex<double> acc(0.0, 0.0);
        for (int i = 0; i < d1; i++)
          for (int j = 0; j < d2; j++)
            for (int k = 0; k < d3; k++) {
              if (C[i][j][k] == 0.0) continue;
              acc += U1[a][i] * U2[b][j] * std::conj(U3[c][k]) * C[i][j][k];
            }
        Rre[a][b][c] = acc.real();
        Rim[a][b][c] = acc.imag();
        if (std::fabs(acc.real()) > mxre) mxre = std::fabs(acc.real());
        if (std::fabs(acc.imag()) > mxim) mxim = std::fabs(acc.imag());
      }
    }
  }
  const bool use_im = mxim > mxre;
  for (int a = 0; a < d1; a++)
    for (int b = 0; b < d2; b++)
      for (int c = 0; c < d3; c++) {
        const float w = (float)(use_im ? Rim[a][b][c] : Rre[a][b][c]);
        R[(a * d2 + b) * d3 + c] = make_float2(w, w);  // duplicate for f32x2
      }
}

static void build_params(Params& p) {
  cg_real_h(0, 0, 0, &p.c000[0][0][0]);
  cg_real_h(1, 1, 0, &p.c110[0][0][0]);
  cg_real_h(2, 2, 0, &p.c220[0][0][0]);
  cg_real_h(0, 1, 1, &p.c011[0][0][0]);
  cg_real_h(1, 2, 1, &p.c121[0][0][0]);
  cg_real_h(0, 2, 2, &p.c022[0][0][0]);
  cg_real_h(1, 1, 2, &p.c112[0][0][0]);
  cg_real_h(1, 2, 2, &p.c122[0][0][0]);
  cg_real_h(2, 2, 2, &p.c222[0][0][0]);
  cg_real_h(1, 2, 3, &p.c123[0][0][0]);
  cg_real_h(2, 2, 4, &p.c224[0][0][0]);
}

// ============================================================================
extern "C" void kernel_launch(void* const* d_in, const int* in_sizes, int n_in,
                              void* d_out, int out_size) {
  (void)n_in;
  (void)out_size;
  const u64* x = (const u64*)d_in[0];       // (B, 1152) fp32 = 576 u64/row
  const u64* keep = (const u64*)d_in[1];    // (384,)
  const u64* mix = (const u64*)d_in[2];     // (2432,)
  u64* out = (u64*)d_out;                   // (B, 3200) fp32 = 1600 u64/row

  const int B = in_sizes[0] / 1152;
  Params p;
  build_params(p);

  const int nthreads = B * 64;              // 2 channels per thread (1 f32x2 lane)
  const int block = 256;
  const int grid = (nthreads + block - 1) / block;
  selfmix_kernel<<<grid, block>>>(x, keep, mix, out, nthreads, p);
}